// round 5
// baseline (speedup 1.0000x reference)
#include <cuda_runtime.h>
#include <math.h>

// Problem constants
#define Hn    81
#define G3    243          // 3*H
#define RPAD  244
#define NPAIR 122
#define Fn    128
#define Tn    1024
#define Bn    512
#define BPC   4
#define NCTA  128          // 512/4

// ---- gemm v4 config ----
#define GT4      512
#define WPITCH   260       // floats per k-row (130 pairs)
#define XPITCH   69        // floats per k-row of x tile (64 cols + 5 pad)
#define TSUB     16        // timesteps per subtile (64 cols)
#define NSUB     8         // subtiles per CTA -> 128 t per CTA

#define GSM_W    (Fn * WPITCH * 4)            // 133120 B
#define GSM_X    (Fn * XPITCH * 4)            // 35328 B per buffer
#define GSM4_BYTES (GSM_W + 2 * GSM_X)        // 203776 B

// ---- recurrence v3 config ----
#define RT3    512

// =====================================================================
// Device scratch: XG[t][ctab][r(244)] float4(4 batches) = 512 MB
// =====================================================================
__device__ float4 g_xg[Tn * NCTA * RPAD];
__device__ float g_h8[Bn * 8];

// ---------- packed f32x2 helpers ----------
static __device__ __forceinline__ unsigned long long dup2(float x) {
    unsigned long long r;
    asm("mov.b64 %0, {%1, %1};" : "=l"(r) : "f"(x));
    return r;
}
static __device__ __forceinline__ void ffma2(unsigned long long &d,
                                             unsigned long long a,
                                             unsigned long long b) {
    asm("fma.rn.f32x2 %0, %1, %2, %0;" : "+l"(d) : "l"(a), "l"(b));
}
static __device__ __forceinline__ unsigned long long addx2(unsigned long long a,
                                                           unsigned long long b) {
    unsigned long long r;
    asm("add.rn.f32x2 %0, %1, %2;" : "=l"(r) : "l"(a), "l"(b));
    return r;
}
static __device__ __forceinline__ float2 unpk(unsigned long long v) {
    float lo, hi;
    asm("mov.b64 {%0, %1}, %2;" : "=f"(lo), "=f"(hi) : "l"(v));
    return make_float2(lo, hi);
}

// ---------- fast activations ----------
static __device__ __forceinline__ float sigm(float x) {
    x = fminf(fmaxf(x, -30.f), 30.f);
    return __fdividef(1.f, 1.f + __expf(-x));
}
static __device__ __forceinline__ float tanh_f(float x) {
    x = fminf(fmaxf(x, -20.f), 20.f);
    float e = __expf(-2.f * x);
    return __fdividef(1.f - e, 1.f + e);
}

// =====================================================================
// Kernel 1 (v4): XG = x @ W_ih^T + b_ih, register-tiled, 512 threads.
// CTA: 128 row-pairs x 64 cols (16 t x 4 b), 8 subtiles. 1 CTA/SM,
// 4 warps/SMSP. Thread: 4 pairs x 4 cols = 16 FFMA2/k; per warp-k:
// 2 LDS.128(w) + 4 LDS.32(x) + 4 dup + 16 FFMA2 -> 26 issues / 32 fma.
// =====================================================================
__global__ void __launch_bounds__(GT4) xg_gemm4(
    const float* __restrict__ x,     // [B,1,T,F]
    const float* __restrict__ W_ih,  // [3H,F]
    const float* __restrict__ b_ih)  // [3H]
{
    extern __shared__ char sm[];
    float* wsm = (float*)sm;                        // [k][260]
    float* xsm = (float*)(sm + GSM_W);              // 2 bufs [k][69]

    const int tid  = threadIdx.x;
    const int tx   = tid & 15;       // col group: cols tx + 16j
    const int ty   = tid >> 4;       // pair group (0..31): pairs 4ty..4ty+3
    const int ctab = blockIdx.x;
    const int b0   = ctab * BPC;
    const int tch  = blockIdx.y * (NSUB * TSUB);

    // zero + stage W_ih^T row-paired
    for (int i = tid; i < Fn * WPITCH; i += GT4) wsm[i] = 0.f;
    __syncthreads();
    for (int idx = tid; idx < G3 * Fn; idx += GT4) {
        int k = idx & (Fn - 1);
        int r = idx >> 7;
        wsm[k * WPITCH + (r >> 1) * 2 + (r & 1)] = W_ih[r * Fn + k];
    }

    float bi0[4], bi1[4];
    #pragma unroll
    for (int p = 0; p < 4; p++) {
        int P = ty * 4 + p;
        bi0[p] = (2 * P < G3)     ? b_ih[2 * P]     : 0.f;
        bi1[p] = (2 * P + 1 < G3) ? b_ih[2 * P + 1] : 0.f;
    }

    // x loader mapping: lane-contiguous along k for coalesced LDG.128
    const int lk4 = tid & 31;
    const int lc  = tid >> 5;        // 0..15; cols lc + 16m
    const long sbt = (long)Tn * Fn;

    // stage subtile 0
    {
        #pragma unroll
        for (int m = 0; m < 4; m++) {
            int c  = lc + 16 * m;
            int b  = c & 3, tl = c >> 2;
            float4 v = *(const float4*)(x + (long)(b0 + b) * sbt
                                        + (long)(tch + tl) * Fn + lk4 * 4);
            float* dst = xsm + c;
            dst[(lk4 * 4 + 0) * XPITCH] = v.x;
            dst[(lk4 * 4 + 1) * XPITCH] = v.y;
            dst[(lk4 * 4 + 2) * XPITCH] = v.z;
            dst[(lk4 * 4 + 3) * XPITCH] = v.w;
        }
    }
    __syncthreads();

    for (int s = 0; s < NSUB; s++) {
        const int cur = s & 1, nxt = cur ^ 1;
        const int t0 = tch + s * TSUB;

        // prefetch next subtile into regs
        float4 qv[4];
        const bool pf = (s + 1 < NSUB);
        if (pf) {
            const int tn0 = t0 + TSUB;
            #pragma unroll
            for (int m = 0; m < 4; m++) {
                int c = lc + 16 * m;
                int b = c & 3, tl = c >> 2;
                qv[m] = *(const float4*)(x + (long)(b0 + b) * sbt
                                         + (long)(tn0 + tl) * Fn + lk4 * 4);
            }
        }

        // main compute: 4 pairs x 4 cols, K = 128
        unsigned long long acc[4][4];
        #pragma unroll
        for (int p = 0; p < 4; p++)
            #pragma unroll
            for (int j = 0; j < 4; j++) acc[p][j] = 0ull;

        const float* xb = xsm + cur * (Fn * XPITCH) + tx;
        const float* wb = wsm + ty * 8;

        #pragma unroll 8
        for (int k = 0; k < Fn; k++) {
            const ulonglong2 w01 = *(const ulonglong2*)(wb + k * WPITCH);
            const ulonglong2 w23 = *(const ulonglong2*)(wb + k * WPITCH + 4);
            unsigned long long xd[4];
            #pragma unroll
            for (int j = 0; j < 4; j++) xd[j] = dup2(xb[k * XPITCH + 16 * j]);
            #pragma unroll
            for (int j = 0; j < 4; j++) {
                ffma2(acc[0][j], w01.x, xd[j]);
                ffma2(acc[1][j], w01.y, xd[j]);
                ffma2(acc[2][j], w23.x, xd[j]);
                ffma2(acc[3][j], w23.y, xd[j]);
            }
        }

        // store (+bias)
        {
            float* gout = (float*)g_xg;
            const int b  = tx & 3;
            const int ta = tx >> 2;
            #pragma unroll
            for (int p = 0; p < 4; p++) {
                int P = ty * 4 + p;
                if (P < NPAIR) {
                    int r0 = 2 * P;
                    #pragma unroll
                    for (int j = 0; j < 4; j++) {
                        int t = t0 + ta + 4 * j;
                        long base = ((long)t * NCTA + ctab) * RPAD;
                        float2 u = unpk(acc[p][j]);
                        gout[(base + r0) * 4 + b]     = u.x + bi0[p];
                        gout[(base + r0 + 1) * 4 + b] = u.y + bi1[p];
                    }
                }
            }
        }

        if (pf) {
            #pragma unroll
            for (int m = 0; m < 4; m++) {
                float* dst = xsm + nxt * (Fn * XPITCH) + lc + 16 * m;
                dst[(lk4 * 4 + 0) * XPITCH] = qv[m].x;
                dst[(lk4 * 4 + 1) * XPITCH] = qv[m].y;
                dst[(lk4 * 4 + 2) * XPITCH] = qv[m].z;
                dst[(lk4 * 4 + 3) * XPITCH] = qv[m].w;
            }
        }
        __syncthreads();
    }
}

// =====================================================================
// Kernel 2 (v3): recurrence. 128 CTAs x 512 threads.
// Thread = (pair p = tid>>2, k-quarter kq = tid&3). Weights pre-dup'd
// as packed f32x2 in regs. Inner iter: 1 LDS.128 + 4 FFMA2.
// Reduce over kq via shfl.xor 1,2 (kq in lane bits 0-1).
// =====================================================================
__global__ void __launch_bounds__(RT3, 1) gru_rec3(
    const float* __restrict__ W_hh,  // [3H,H]
    const float* __restrict__ b_hh,  // [3H]
    const float* __restrict__ fc_w,  // [8,H]
    const float* __restrict__ fc_b)  // [8]
{
    __shared__ float4 hs4[84];
    __shared__ float4 hg4[RPAD];
    __shared__ float4 xgs[2 * RPAD];

    const int tid  = threadIdx.x;
    const int ctab = blockIdx.x;
    const int p    = tid >> 2;       // 0..127 (valid < 122)
    const int kq   = tid & 3;
    const int kb   = kq * 21;        // k range [kb, kb+21), zero-padded
    const int r0 = 2 * p, r1 = 2 * p + 1;

    // weights pre-duplicated into packed pairs (84 regs)
    unsigned long long w0d[21], w1d[21];
    #pragma unroll
    for (int i = 0; i < 21; i++) {
        int k = kb + i;
        bool kok = (k < Hn);
        w0d[i] = dup2((kok && r0 < G3) ? W_hh[r0 * Hn + k] : 0.f);
        w1d[i] = dup2((kok && r1 < G3) ? W_hh[r1 * Hn + k] : 0.f);
    }
    const float bh0 = (r0 < G3) ? b_hh[r0] : 0.f;
    const float bh1 = (r1 < G3) ? b_hh[r1] : 0.f;

    if (tid < 84) hs4[tid] = make_float4(0.f, 0.f, 0.f, 0.f);
    if (tid < RPAD) xgs[tid] = g_xg[(long)ctab * RPAD + tid];
    __syncthreads();

    float* hs_f = (float*)hs4;

    for (int t = 0; t < Tn; t++) {
        const int cur = t & 1, nxt = cur ^ 1;

        float4 q = make_float4(0.f, 0.f, 0.f, 0.f);
        const bool pf = (t + 1 < Tn);
        if (pf && tid < RPAD)
            q = g_xg[((long)(t + 1) * NCTA + ctab) * RPAD + tid];

        unsigned long long c00 = 0, c01 = 0, c10 = 0, c11 = 0;
        const ulonglong2* hp = (const ulonglong2*)hs4;
        #pragma unroll
        for (int i = 0; i < 21; i++) {
            ulonglong2 hv = hp[kb + i];
            ffma2(c00, w0d[i], hv.x); ffma2(c01, w0d[i], hv.y);
            ffma2(c10, w1d[i], hv.x); ffma2(c11, w1d[i], hv.y);
        }
        // reduce across k-quarters (lane bits 0-1)
        c00 = addx2(c00, __shfl_xor_sync(0xffffffffu, c00, 1));
        c01 = addx2(c01, __shfl_xor_sync(0xffffffffu, c01, 1));
        c10 = addx2(c10, __shfl_xor_sync(0xffffffffu, c10, 1));
        c11 = addx2(c11, __shfl_xor_sync(0xffffffffu, c11, 1));
        c00 = addx2(c00, __shfl_xor_sync(0xffffffffu, c00, 2));
        c01 = addx2(c01, __shfl_xor_sync(0xffffffffu, c01, 2));
        c10 = addx2(c10, __shfl_xor_sync(0xffffffffu, c10, 2));
        c11 = addx2(c11, __shfl_xor_sync(0xffffffffu, c11, 2));

        if (kq == 0 && p < NPAIR) {
            float2 u0 = unpk(c00), u1 = unpk(c01), u2 = unpk(c10), u3 = unpk(c11);
            hg4[r0] = make_float4(u0.x + bh0, u0.y + bh0, u1.x + bh0, u1.y + bh0);
            hg4[r1] = make_float4(u2.x + bh1, u2.y + bh1, u3.x + bh1, u3.y + bh1);
        }
        if (pf && tid < RPAD) xgs[nxt * RPAD + tid] = q;
        __syncthreads();

        // gate combine: 324 items over 512 threads (single round)
        if (tid < Hn * 4) {
            const float* xgc = (const float*)(xgs + cur * RPAD);
            const float* hgf = (const float*)hg4;
            float xr = xgc[tid],       hr = hgf[tid];
            float xz = xgc[324 + tid], hz = hgf[324 + tid];
            float xn = xgc[648 + tid], hn = hgf[648 + tid];
            float r = sigm(xr + hr);
            float z = sigm(xz + hz);
            float n = tanh_f(xn + r * hn);
            hs_f[tid] = (1.f - z) * n + z * hs_f[tid];
        }
        __syncthreads();
    }

    // head stage 1: out8 = silu(h_last @ fc_w^T + fc_b)
    if (tid < 32) {
        int b = tid >> 3, f = tid & 7;
        float a = fc_b[f];
        #pragma unroll 27
        for (int j = 0; j < Hn; j++) a += hs_f[j * 4 + b] * fc_w[f * Hn + j];
        a = a * sigm(a);
        g_h8[(ctab * BPC + b) * 8 + f] = a;
    }
}

// =====================================================================
// Kernel 3: BN(8) -> fc1 -> silu -> BN(4) -> fc2. One CTA, 512 threads.
// =====================================================================
__global__ void __launch_bounds__(Bn) head_kernel(
    const float* __restrict__ g1, const float* __restrict__ beta1,
    const float* __restrict__ fc1_w, const float* __restrict__ fc1_b,
    const float* __restrict__ g2, const float* __restrict__ beta2,
    const float* __restrict__ fc2_w, const float* __restrict__ fc2_b,
    float* __restrict__ out)
{
    __shared__ float s8[Bn * 8];
    __shared__ float s4[Bn * 4];
    __shared__ float mu1[8], iv1[8], mu2[4], iv2[4];
    const int tid = threadIdx.x;

    for (int i = tid; i < Bn * 8; i += Bn) s8[i] = g_h8[i];
    __syncthreads();

    if (tid < 8) {
        float s = 0.f, ss = 0.f;
        for (int b = 0; b < Bn; b++) { float v = s8[b * 8 + tid]; s += v; ss += v * v; }
        float m = s * (1.f / Bn);
        float var = ss * (1.f / Bn) - m * m;
        mu1[tid] = m;
        iv1[tid] = rsqrtf(var + 1e-5f);
    }
    __syncthreads();

    {
        int b = tid;
        float y[8];
        #pragma unroll
        for (int f = 0; f < 8; f++)
            y[f] = (s8[b * 8 + f] - mu1[f]) * iv1[f] * g1[f] + beta1[f];
        #pragma unroll
        for (int o = 0; o < 4; o++) {
            float a = fc1_b[o];
            #pragma unroll
            for (int f = 0; f < 8; f++) a += y[f] * fc1_w[o * 8 + f];
            a = a * sigm(a);
            s4[b * 4 + o] = a;
        }
    }
    __syncthreads();

    if (tid < 4) {
        float s = 0.f, ss = 0.f;
        for (int b = 0; b < Bn; b++) { float v = s4[b * 4 + tid]; s += v; ss += v * v; }
        float m = s * (1.f / Bn);
        float var = ss * (1.f / Bn) - m * m;
        mu2[tid] = m;
        iv2[tid] = rsqrtf(var + 1e-5f);
    }
    __syncthreads();

    {
        int b = tid;
        float a = fc2_b[0];
        #pragma unroll
        for (int o = 0; o < 4; o++)
            a += ((s4[b * 4 + o] - mu2[o]) * iv2[o] * g2[o] + beta2[o]) * fc2_w[o];
        out[b] = a;
    }
}

// =====================================================================
extern "C" void kernel_launch(void* const* d_in, const int* in_sizes, int n_in,
                              void* d_out, int out_size) {
    const float* x     = (const float*)d_in[0];
    const float* W_ih  = (const float*)d_in[1];
    const float* W_hh  = (const float*)d_in[2];
    const float* b_ih  = (const float*)d_in[3];
    const float* b_hh  = (const float*)d_in[4];
    const float* fc_w  = (const float*)d_in[5];
    const float* fc_b  = (const float*)d_in[6];
    const float* g1    = (const float*)d_in[7];
    const float* beta1 = (const float*)d_in[8];
    const float* fc1_w = (const float*)d_in[9];
    const float* fc1_b = (const float*)d_in[10];
    const float* g2    = (const float*)d_in[11];
    const float* beta2 = (const float*)d_in[12];
    const float* fc2_w = (const float*)d_in[13];
    const float* fc2_b = (const float*)d_in[14];
    float* out = (float*)d_out;

    cudaFuncSetAttribute(xg_gemm4, cudaFuncAttributeMaxDynamicSharedMemorySize, GSM4_BYTES);

    xg_gemm4<<<dim3(NCTA, Tn / (NSUB * TSUB)), GT4, GSM4_BYTES>>>(x, W_ih, b_ih);
    gru_rec3<<<NCTA, RT3>>>(W_hh, b_hh, fc_w, fc_b);
    head_kernel<<<1, Bn>>>(g1, beta1, fc1_w, fc1_b, g2, beta2, fc2_w, fc2_b, out);
}

// round 8
// speedup vs baseline: 1.2984x; 1.2984x over previous
#include <cuda_runtime.h>
#include <cuda_bf16.h>
#include <cstdint>
#include <math.h>

// Problem constants
#define Hn    81
#define G3    243          // 3*H
#define RPAD  244
#define NPAIR 122
#define Fn    128
#define Tn    1024
#define Bn    512
#define BPC   4
#define NCTA  128          // 512/4

// recurrence config
#define RT     256

// =====================================================================
// Device scratch: XG[t][ctab][b(4)][r(244)] floats = 512 MB
// =====================================================================
__device__ float4 g_xg[Tn * NCTA * RPAD];
__device__ float g_h8[Bn * 8];

// ---------- packed f32x2 helpers ----------
static __device__ __forceinline__ unsigned long long dup2(float x) {
    unsigned long long r;
    asm("mov.b64 %0, {%1, %1};" : "=l"(r) : "f"(x));
    return r;
}
static __device__ __forceinline__ void ffma2(unsigned long long &d,
                                             unsigned long long a,
                                             unsigned long long b) {
    asm("fma.rn.f32x2 %0, %1, %2, %0;" : "+l"(d) : "l"(a), "l"(b));
}
static __device__ __forceinline__ unsigned long long addx2(unsigned long long a,
                                                           unsigned long long b) {
    unsigned long long r;
    asm("add.rn.f32x2 %0, %1, %2;" : "=l"(r) : "l"(a), "l"(b));
    return r;
}
static __device__ __forceinline__ float2 unpk(unsigned long long v) {
    float lo, hi;
    asm("mov.b64 {%0, %1}, %2;" : "=f"(lo), "=f"(hi) : "l"(v));
    return make_float2(lo, hi);
}

// ---------- fast activations ----------
static __device__ __forceinline__ float sigm(float x) {
    x = fminf(fmaxf(x, -30.f), 30.f);
    return __fdividef(1.f, 1.f + __expf(-x));
}
static __device__ __forceinline__ float tanh_f(float x) {
    x = fminf(fmaxf(x, -20.f), 20.f);
    float e = __expf(-2.f * x);
    return __fdividef(1.f - e, 1.f + e);
}

// =====================================================================
// Kernel 1: XG = x @ W_ih^T + b_ih via mma.sync bf16 (hi/lo split, 3 passes).
// grid (128 ctab, 32 tchunk, 2 mtile) x 256 threads.
// CTA tile: M=128 rows x N=128 cols (32 t x 4 b), K=128 smem-resident.
// Warp tile: 32x64. smem tiles 272B pitch (conflict-free ldmatrix).
// =====================================================================
#define PITCH    272                     // bytes per 128-bf16 row (+8 pad)
#define TILE_SZ  (128 * PITCH)           // 34816
#define SM_AHI   0
#define SM_ALO   (SM_AHI + TILE_SZ)
#define SM_BHI   (SM_ALO + TILE_SZ)
#define SM_BLO   (SM_BHI + TILE_SZ)
#define SM_BS    (4 * TILE_SZ)           // 139264: bias (128 floats)
#define SM_MMA_BYTES (SM_BS + 512)       // 139776
#define CPITCH   132                     // epilogue staging pitch (floats)

static __device__ __forceinline__ uint32_t smem_u32(const void* p) {
    uint32_t a;
    asm("{ .reg .u64 t; cvta.to.shared.u64 t, %1; cvt.u32.u64 %0, t; }"
        : "=r"(a) : "l"(p));
    return a;
}
static __device__ __forceinline__ uint32_t bfpack(float a, float b) {
    uint32_t r;
    asm("cvt.rn.bf16x2.f32 %0, %1, %2;" : "=r"(r) : "f"(b), "f"(a));
    return r;
}
// convert float4 -> hi/lo bf16, store 8B each at byte offset 'off'
static __device__ __forceinline__ void cvt8(char* thi, char* tlo, int off, float4 v) {
    uint32_t h0 = bfpack(v.x, v.y);
    uint32_t h1 = bfpack(v.z, v.w);
    float fx = __uint_as_float(h0 << 16);
    float fy = __uint_as_float(h0 & 0xffff0000u);
    float fz = __uint_as_float(h1 << 16);
    float fw = __uint_as_float(h1 & 0xffff0000u);
    uint32_t l0 = bfpack(v.x - fx, v.y - fy);
    uint32_t l1 = bfpack(v.z - fz, v.w - fw);
    *(uint2*)(thi + off) = make_uint2(h0, h1);
    *(uint2*)(tlo + off) = make_uint2(l0, l1);
}
static __device__ __forceinline__ void ldx4(uint32_t* r, uint32_t addr) {
    asm volatile("ldmatrix.sync.aligned.m8n8.x4.shared.b16 {%0,%1,%2,%3}, [%4];"
                 : "=r"(r[0]), "=r"(r[1]), "=r"(r[2]), "=r"(r[3]) : "r"(addr));
}
static __device__ __forceinline__ void mma16816(float* c, const uint32_t* a,
                                                const uint32_t* b) {
    asm volatile(
        "mma.sync.aligned.m16n8k16.row.col.f32.bf16.bf16.f32 "
        "{%0,%1,%2,%3}, {%4,%5,%6,%7}, {%8,%9}, {%0,%1,%2,%3};"
        : "+f"(c[0]), "+f"(c[1]), "+f"(c[2]), "+f"(c[3])
        : "r"(a[0]), "r"(a[1]), "r"(a[2]), "r"(a[3]), "r"(b[0]), "r"(b[1]));
}

__global__ void __launch_bounds__(256, 1) xg_mma(
    const float* __restrict__ x,     // [B,1,T,F]
    const float* __restrict__ W_ih,  // [3H,F]
    const float* __restrict__ b_ih)  // [3H]
{
    extern __shared__ char sm[];
    const uint32_t smb = smem_u32(sm);
    float* bsm = (float*)(sm + SM_BS);

    const int tid  = threadIdx.x;
    const int lane = tid & 31;
    const int w    = tid >> 5;
    const int ctab = blockIdx.x;
    const int b0   = ctab * BPC;
    const int t0   = blockIdx.y * 32;
    const int mt   = blockIdx.z;
    const long sbt = (long)Tn * Fn;

    // ---- stage A (this mtile's 128 W rows, hi/lo) and B (x cols, hi/lo) ----
    {
        const int r2 = tid >> 1;     // row / col index 0..127
        const int kh = tid & 1;      // k half (64 each)
        // A
        {
            int rg = mt * 128 + r2;
            char* thi = sm + SM_AHI;
            char* tlo = sm + SM_ALO;
            const float4* src = (const float4*)(W_ih + (long)rg * Fn);
            bool valid = (rg < G3);
            #pragma unroll
            for (int i = 0; i < 16; i++) {
                int k = kh * 64 + i * 4;
                float4 v = valid ? src[k >> 2] : make_float4(0.f, 0.f, 0.f, 0.f);
                cvt8(thi, tlo, r2 * PITCH + k * 2, v);
            }
        }
        // B: col n = r2 = t_local*4 + b
        {
            int b = r2 & 3, tl = r2 >> 2;
            char* thi = sm + SM_BHI;
            char* tlo = sm + SM_BLO;
            const float4* src = (const float4*)(x + (long)(b0 + b) * sbt
                                                + (long)(t0 + tl) * Fn);
            #pragma unroll
            for (int i = 0; i < 16; i++) {
                int k = kh * 64 + i * 4;
                cvt8(thi, tlo, r2 * PITCH + k * 2, src[k >> 2]);
            }
        }
        if (tid < 128) {
            int rg = mt * 128 + tid;
            bsm[tid] = (rg < G3) ? b_ih[rg] : 0.f;
        }
    }
    __syncthreads();

    // ---- warp-tiled mma: warp (w&3) -> m, (w>>2) -> n ----
    const int wm = (w & 3) * 32;
    const int wn = (w >> 2) * 64;

    float c[2][8][4];
    #pragma unroll
    for (int mb = 0; mb < 2; mb++)
        #pragma unroll
        for (int nb = 0; nb < 8; nb++)
            #pragma unroll
            for (int q = 0; q < 4; q++) c[mb][nb][q] = 0.f;

    int aoff[2], boff[4];
    {
        int lr = lane & 15, lk8 = (lane >> 4) * 8;
        aoff[0] = (wm + lr) * PITCH + lk8 * 2;
        aoff[1] = (wm + 16 + lr) * PITCH + lk8 * 2;
        int sel = lane >> 3;
        int nrow = wn + (lane & 7) + (sel >> 1) * 8;
        int kk = (sel & 1) * 8;
        #pragma unroll
        for (int g = 0; g < 4; g++)
            boff[g] = (nrow + 16 * g) * PITCH + kk * 2;
    }

    const uint32_t abase[3] = { smb + SM_AHI, smb + SM_ALO, smb + SM_AHI };
    const uint32_t bbase[3] = { smb + SM_BHI, smb + SM_BHI, smb + SM_BLO };

    #pragma unroll 1
    for (int pass = 0; pass < 3; pass++) {
        const uint32_t Ab = abase[pass], Bb = bbase[pass];
        #pragma unroll 1
        for (int ks = 0; ks < 8; ks++) {
            const int kb = ks * 32;   // 16 bf16 = 32 bytes
            uint32_t a[2][4], bb[8][2];
            ldx4(a[0], Ab + aoff[0] + kb);
            ldx4(a[1], Ab + aoff[1] + kb);
            #pragma unroll
            for (int g = 0; g < 4; g++) {
                uint32_t r4[4];
                ldx4(r4, Bb + boff[g] + kb);
                bb[2 * g][0] = r4[0]; bb[2 * g][1] = r4[1];
                bb[2 * g + 1][0] = r4[2]; bb[2 * g + 1][1] = r4[3];
            }
            #pragma unroll
            for (int mb = 0; mb < 2; mb++)
                #pragma unroll
                for (int nb = 0; nb < 8; nb++)
                    mma16816(c[mb][nb], a[mb], bb[nb]);
        }
    }

    // ---- epilogue: transpose via smem (conflict-free), coalesced store ----
    __syncthreads();    // all smem tile reads complete
    float* Cs = (float*)sm;   // [col(128)][CPITCH]
    {
        int lr = lane >> 2;
        int lc = (lane & 3) * 2;
        #pragma unroll
        for (int mb = 0; mb < 2; mb++) {
            int row = wm + 16 * mb + lr;
            #pragma unroll
            for (int nb = 0; nb < 8; nb++) {
                int col = wn + 8 * nb + lc;
                Cs[col * CPITCH + row]           = c[mb][nb][0];
                Cs[(col + 1) * CPITCH + row]     = c[mb][nb][1];
                Cs[col * CPITCH + row + 8]       = c[mb][nb][2];
                Cs[(col + 1) * CPITCH + row + 8] = c[mb][nb][3];
            }
        }
    }
    __syncthreads();
    {
        float* gxf = (float*)g_xg;
        int n  = tid >> 1;         // col 0..127
        int rh = tid & 1;
        int tl = n >> 2, b = n & 3;
        long gbase = ((long)(t0 + tl) * NCTA + ctab) * 976 + b * 244 + mt * 128;
        int i0 = rh * 16;
        int i1 = rh ? ((mt == 0) ? 32 : 29) : 16;   // mtile1: rows 128..243
        for (int i = i0; i < i1; i++) {
            float4 cv = *(float4*)(Cs + n * CPITCH + 4 * i);
            float4 bv = *(float4*)(bsm + 4 * i);
            cv.x += bv.x; cv.y += bv.y; cv.z += bv.z; cv.w += bv.w;
            *(float4*)(gxf + gbase + 4 * i) = cv;
        }
    }
}

// =====================================================================
// Kernel 2: recurrence. 128 CTAs x 256 threads. XG layout [t][ctab][b][r].
// =====================================================================
__global__ void __launch_bounds__(RT, 1) gru_rec(
    const float* __restrict__ W_hh,  // [3H,H]
    const float* __restrict__ b_hh,  // [3H]
    const float* __restrict__ fc_w,  // [8,H]
    const float* __restrict__ fc_b)  // [8]
{
    __shared__ float4 hs4[84];
    __shared__ float4 hg4[RPAD];
    __shared__ float4 xgs[2 * RPAD];   // per buffer: [b(4)][r(244)] floats

    const int tid  = threadIdx.x;
    const int lane = tid & 31;
    const int warp = tid >> 5;
    const int ctab = blockIdx.x;

    const int p     = warp * 16 + (lane >> 1);
    const int kh    = lane & 1;
    const int kbase = kh * 41;
    const int r0 = 2 * p, r1 = 2 * p + 1;

    float wr0[41], wr1[41];
    #pragma unroll
    for (int i = 0; i < 41; i++) {
        int k = kbase + i;
        bool kok = (k < Hn);
        wr0[i] = (kok && r0 < G3) ? W_hh[r0 * Hn + k] : 0.f;
        wr1[i] = (kok && r1 < G3) ? W_hh[r1 * Hn + k] : 0.f;
    }
    const float bh0 = (r0 < G3) ? b_hh[r0] : 0.f;
    const float bh1 = (r1 < G3) ? b_hh[r1] : 0.f;

    if (tid < 84) hs4[tid] = make_float4(0.f, 0.f, 0.f, 0.f);
    if (tid < RPAD) xgs[tid] = g_xg[(long)ctab * RPAD + tid];
    __syncthreads();

    float* hs_f = (float*)hs4;

    for (int t = 0; t < Tn; t++) {
        const int cur = t & 1, nxt = cur ^ 1;

        float4 q = make_float4(0.f, 0.f, 0.f, 0.f);
        const bool pf = (t + 1 < Tn);
        if (pf && tid < RPAD)
            q = g_xg[((long)(t + 1) * NCTA + ctab) * RPAD + tid];

        unsigned long long c00 = 0, c01 = 0, c10 = 0, c11 = 0;
        const ulonglong2* hp = (const ulonglong2*)hs4;
        #pragma unroll
        for (int i = 0; i < 41; i++) {
            ulonglong2 hv = hp[kbase + i];
            unsigned long long w0 = dup2(wr0[i]);
            unsigned long long w1 = dup2(wr1[i]);
            ffma2(c00, w0, hv.x); ffma2(c01, w0, hv.y);
            ffma2(c10, w1, hv.x); ffma2(c11, w1, hv.y);
        }
        c00 = addx2(c00, __shfl_xor_sync(0xffffffffu, c00, 1));
        c01 = addx2(c01, __shfl_xor_sync(0xffffffffu, c01, 1));
        c10 = addx2(c10, __shfl_xor_sync(0xffffffffu, c10, 1));
        c11 = addx2(c11, __shfl_xor_sync(0xffffffffu, c11, 1));

        if (kh == 0 && p < NPAIR) {
            float2 u0 = unpk(c00), u1 = unpk(c01), u2 = unpk(c10), u3 = unpk(c11);
            hg4[r0] = make_float4(u0.x + bh0, u0.y + bh0, u1.x + bh0, u1.y + bh0);
            hg4[r1] = make_float4(u2.x + bh1, u2.y + bh1, u3.x + bh1, u3.y + bh1);
        }
        if (pf && tid < RPAD) xgs[nxt * RPAD + tid] = q;
        __syncthreads();

        // gate combine: item (r, b); xg indexed [b][r], hg/hs [r][b]
        const float* xgc = (const float*)(xgs + cur * RPAD);
        const float* hgf = (const float*)hg4;
        #pragma unroll
        for (int rep = 0; rep < 2; rep++) {
            int it = tid + rep * RT;
            if (it < Hn * 4) {
                int r = it >> 2, b = it & 3;
                float xr = xgc[b * RPAD + r];
                float xz = xgc[b * RPAD + Hn + r];
                float xn = xgc[b * RPAD + 2 * Hn + r];
                float hr = hgf[it];
                float hz = hgf[Hn * 4 + it];
                float hn = hgf[2 * Hn * 4 + it];
                float rr = sigm(xr + hr);
                float z  = sigm(xz + hz);
                float n  = tanh_f(xn + rr * hn);
                hs_f[it] = (1.f - z) * n + z * hs_f[it];
            }
        }
        __syncthreads();
    }

    if (tid < 32) {
        int b = tid >> 3, f = tid & 7;
        float a = fc_b[f];
        #pragma unroll 27
        for (int j = 0; j < Hn; j++) a += hs_f[j * 4 + b] * fc_w[f * Hn + j];
        a = a * sigm(a);
        g_h8[(ctab * BPC + b) * 8 + f] = a;
    }
}

// =====================================================================
// Kernel 3: BN(8) -> fc1 -> silu -> BN(4) -> fc2. One CTA, 512 threads.
// =====================================================================
__global__ void __launch_bounds__(Bn) head_kernel(
    const float* __restrict__ g1, const float* __restrict__ beta1,
    const float* __restrict__ fc1_w, const float* __restrict__ fc1_b,
    const float* __restrict__ g2, const float* __restrict__ beta2,
    const float* __restrict__ fc2_w, const float* __restrict__ fc2_b,
    float* __restrict__ out)
{
    __shared__ float s8[Bn * 8];
    __shared__ float s4[Bn * 4];
    __shared__ float mu1[8], iv1[8], mu2[4], iv2[4];
    const int tid = threadIdx.x;

    for (int i = tid; i < Bn * 8; i += Bn) s8[i] = g_h8[i];
    __syncthreads();

    if (tid < 8) {
        float s = 0.f, ss = 0.f;
        for (int b = 0; b < Bn; b++) { float v = s8[b * 8 + tid]; s += v; ss += v * v; }
        float m = s * (1.f / Bn);
        float var = ss * (1.f / Bn) - m * m;
        mu1[tid] = m;
        iv1[tid] = rsqrtf(var + 1e-5f);
    }
    __syncthreads();

    {
        int b = tid;
        float y[8];
        #pragma unroll
        for (int f = 0; f < 8; f++)
            y[f] = (s8[b * 8 + f] - mu1[f]) * iv1[f] * g1[f] + beta1[f];
        #pragma unroll
        for (int o = 0; o < 4; o++) {
            float a = fc1_b[o];
            #pragma unroll
            for (int f = 0; f < 8; f++) a += y[f] * fc1_w[o * 8 + f];
            a = a * sigm(a);
            s4[b * 4 + o] = a;
        }
    }
    __syncthreads();

    if (tid < 4) {
        float s = 0.f, ss = 0.f;
        for (int b = 0; b < Bn; b++) { float v = s4[b * 4 + tid]; s += v; ss += v * v; }
        float m = s * (1.f / Bn);
        float var = ss * (1.f / Bn) - m * m;
        mu2[tid] = m;
        iv2[tid] = rsqrtf(var + 1e-5f);
    }
    __syncthreads();

    {
        int b = tid;
        float a = fc2_b[0];
        #pragma unroll
        for (int o = 0; o < 4; o++)
            a += ((s4[b * 4 + o] - mu2[o]) * iv2[o] * g2[o] + beta2[o]) * fc2_w[o];
        out[b] = a;
    }
}

// =====================================================================
extern "C" void kernel_launch(void* const* d_in, const int* in_sizes, int n_in,
                              void* d_out, int out_size) {
    const float* x     = (const float*)d_in[0];
    const float* W_ih  = (const float*)d_in[1];
    const float* W_hh  = (const float*)d_in[2];
    const float* b_ih  = (const float*)d_in[3];
    const float* b_hh  = (const float*)d_in[4];
    const float* fc_w  = (const float*)d_in[5];
    const float* fc_b  = (const float*)d_in[6];
    const float* g1    = (const float*)d_in[7];
    const float* beta1 = (const float*)d_in[8];
    const float* fc1_w = (const float*)d_in[9];
    const float* fc1_b = (const float*)d_in[10];
    const float* g2    = (const float*)d_in[11];
    const float* beta2 = (const float*)d_in[12];
    const float* fc2_w = (const float*)d_in[13];
    const float* fc2_b = (const float*)d_in[14];
    float* out = (float*)d_out;

    cudaFuncSetAttribute(xg_mma, cudaFuncAttributeMaxDynamicSharedMemorySize, SM_MMA_BYTES);

    xg_mma<<<dim3(NCTA, 32, 2), 256, SM_MMA_BYTES>>>(x, W_ih, b_ih);
    gru_rec<<<NCTA, RT>>>(W_hh, b_hh, fc_w, fc_b);
    head_kernel<<<1, Bn>>>(g1, beta1, fc1_w, fc1_b, g2, beta2, fc2_w, fc2_b, out);
}